// round 5
// baseline (speedup 1.0000x reference)
#include <cuda_runtime.h>
#include <cuda_bf16.h>

#define NN 50000
#define NE 800000

__device__ int   g_cnt[NN];          // in-degree histogram (excl. self-loop)
__device__ int   g_off[NN + 1];      // CSR offsets
__device__ int   g_cur[NN];          // fill cursors
__device__ int   g_csr_row[NE];      // source node per CSR slot
__device__ float g_dinv[NN];
__device__ float g_H[NN * 128];      // linear output of current layer
__device__ float g_hidden[NN * 128]; // relu(layer1) activations
__device__ float g_W23[128 * 128];   // packed [W2 | W3]

// ---------------------------------------------------------------------------
// CSR build: histogram -> scan (+dinv) -> fill
// ---------------------------------------------------------------------------
__global__ void zero_cnt_kernel() {
    int i = blockIdx.x * blockDim.x + threadIdx.x;
    if (i < NN) g_cnt[i] = 0;
}

__global__ void hist_kernel(const int* __restrict__ ei) {
    int e = blockIdx.x * blockDim.x + threadIdx.x;
    if (e < NE) atomicAdd(&g_cnt[ei[NE + e]], 1);
}

// Single block, 1024 threads: exclusive scan of g_cnt + cursors + dinv.
__global__ void scan_kernel() {
    __shared__ int ssum[1024];
    const int t = threadIdx.x;
    const int CH = (NN + 1023) / 1024;  // 49
    int lo = t * CH;
    int hi = min(lo + CH, NN);
    int sum = 0;
    for (int k = lo; k < hi; k++) sum += g_cnt[k];
    ssum[t] = sum;
    __syncthreads();
    for (int d = 1; d < 1024; d <<= 1) {
        int v = ssum[t];
        int add = (t >= d) ? ssum[t - d] : 0;
        __syncthreads();
        ssum[t] = v + add;
        __syncthreads();
    }
    int run = (t > 0) ? ssum[t - 1] : 0;
    for (int k = lo; k < hi; k++) {
        g_off[k] = run;
        g_cur[k] = run;
        g_dinv[k] = rsqrtf((float)(1 + g_cnt[k]));  // deg includes self-loop
        run += g_cnt[k];
    }
    if (t == 1023) g_off[NN] = run;
}

__global__ void fill_kernel(const int* __restrict__ ei) {
    int e = blockIdx.x * blockDim.x + threadIdx.x;
    if (e < NE) {
        int row = ei[e];
        int col = ei[NE + e];
        int pos = atomicAdd(&g_cur[col], 1);
        g_csr_row[pos] = row;
    }
}

// ---------------------------------------------------------------------------
// Pack [W2 | W3] (each [128,64]) into canonical g_W23 [128,128].
// ---------------------------------------------------------------------------
__global__ void packW_kernel(const float* __restrict__ W2,
                             const float* __restrict__ W3) {
    int i = blockIdx.x * blockDim.x + threadIdx.x;  // over 128*32 float4
    if (i < 128 * 32) {
        int k  = i >> 5;
        int c4 = (i & 31) << 2;
        float4 v;
        if (c4 < 64) v = *(const float4*)(W2 + k * 64 + c4);
        else         v = *(const float4*)(W3 + k * 64 + (c4 - 64));
        ((float4*)g_W23)[i] = v;
    }
}

// ---------------------------------------------------------------------------
// GEMM: g_H = X @ W.  X [NN,128] (x or g_hidden), W [128,128] (W1 or g_W23).
// Only the X tile lives in smem (32 KB -> 3 blocks/SM); W is read via __ldg
// and stays L1-resident (64 KB, shared by all warps).
// Block: 256 threads, 64 rows x 128 cols; thread = 8 rows x 4 cols.
// ---------------------------------------------------------------------------
__global__ __launch_bounds__(256, 3)
void gemm_kernel(const float* __restrict__ Xin,
                 const float* __restrict__ Win,
                 int use_hidden, int use_w23) {
    __shared__ float4 sx[64 * 32];   // 32 KB

    const float4* X4 = (const float4*)(use_hidden ? g_hidden : Xin);
    const float4* W4 = (const float4*)(use_w23 ? g_W23 : Win);

    const int tid = threadIdx.x;
    const int tx = tid & 31;         // cols tx*4 .. tx*4+3
    const int ty = tid >> 5;         // row group base
    const int row0 = blockIdx.x * 64;

    for (int i = tid; i < 64 * 32; i += 256) {
        int r  = i >> 5;
        int k4 = i & 31;
        int row = row0 + r;
        sx[i] = (row < NN) ? X4[row * 32 + k4] : make_float4(0.f, 0.f, 0.f, 0.f);
    }
    __syncthreads();

    float acc[8][4];
#pragma unroll
    for (int r = 0; r < 8; r++)
#pragma unroll
        for (int c = 0; c < 4; c++) acc[r][c] = 0.f;

    for (int k4 = 0; k4 < 32; k4++) {
        float4 xv[8];
#pragma unroll
        for (int r = 0; r < 8; r++) xv[r] = sx[(ty + 8 * r) * 32 + k4];
#pragma unroll
        for (int kk = 0; kk < 4; kk++) {
            float4 wv = __ldg(&W4[(k4 * 4 + kk) * 32 + tx]);
#pragma unroll
            for (int r = 0; r < 8; r++) {
                float xs = (kk == 0) ? xv[r].x : (kk == 1) ? xv[r].y
                          : (kk == 2) ? xv[r].z : xv[r].w;
                acc[r][0] += xs * wv.x;
                acc[r][1] += xs * wv.y;
                acc[r][2] += xs * wv.z;
                acc[r][3] += xs * wv.w;
            }
        }
    }

#pragma unroll
    for (int r = 0; r < 8; r++) {
        int row = row0 + ty + 8 * r;
        if (row < NN) {
            float4 h = make_float4(acc[r][0], acc[r][1], acc[r][2], acc[r][3]);
            *(float4*)(g_H + row * 128 + tx * 4) = h;
        }
    }
}

// ---------------------------------------------------------------------------
// CSR aggregation, fused epilogue. One warp per target node.
//   res = dinv[i] * ( dinv[i]*H[i] + sum_e dinv[row_e]*H[row_e] )
// Gathers batched 8-wide (then 4, then 1) for memory-level parallelism.
// layer==1: g_hidden[i] = relu(res + b1)
// layer==2: out[i,:64]=relu(lo+b2); out[NN*64+i*64+:]=relu(hi+b3)
// ---------------------------------------------------------------------------
__global__ void agg_kernel(int layer,
                           const float* __restrict__ bA,
                           const float* __restrict__ bB,
                           float* __restrict__ out) {
    int warp = (blockIdx.x * blockDim.x + threadIdx.x) >> 5;
    if (warp >= NN) return;
    const int lane = threadIdx.x & 31;
    const int i = warp;
    const int s = g_off[i];
    const int e = g_off[i + 1];
    const float di = g_dinv[i];

    float4 hv = *(const float4*)(g_H + i * 128 + lane * 4);
    float4 acc = make_float4(hv.x * di, hv.y * di, hv.z * di, hv.w * di);

    for (int base = s; base < e; base += 32) {
        int j = base + lane;
        int r = 0;
        float w = 0.f;
        if (j < e) { r = g_csr_row[j]; w = g_dinv[r]; }
        int cnt = min(32, e - base);
        int k = 0;
        // 8-wide batches: 8 independent gathers in flight
        for (; k + 8 <= cnt; k += 8) {
            int rr[8]; float ww[8];
#pragma unroll
            for (int u = 0; u < 8; u++) {
                rr[u] = __shfl_sync(0xffffffffu, r, k + u);
                ww[u] = __shfl_sync(0xffffffffu, w, k + u);
            }
            float4 v[8];
#pragma unroll
            for (int u = 0; u < 8; u++)
                v[u] = *(const float4*)(g_H + rr[u] * 128 + lane * 4);
#pragma unroll
            for (int u = 0; u < 8; u++) {
                acc.x += ww[u] * v[u].x;
                acc.y += ww[u] * v[u].y;
                acc.z += ww[u] * v[u].z;
                acc.w += ww[u] * v[u].w;
            }
        }
        // 4-wide
        for (; k + 4 <= cnt; k += 4) {
            int rr[4]; float ww[4];
#pragma unroll
            for (int u = 0; u < 4; u++) {
                rr[u] = __shfl_sync(0xffffffffu, r, k + u);
                ww[u] = __shfl_sync(0xffffffffu, w, k + u);
            }
            float4 v[4];
#pragma unroll
            for (int u = 0; u < 4; u++)
                v[u] = *(const float4*)(g_H + rr[u] * 128 + lane * 4);
#pragma unroll
            for (int u = 0; u < 4; u++) {
                acc.x += ww[u] * v[u].x;
                acc.y += ww[u] * v[u].y;
                acc.z += ww[u] * v[u].z;
                acc.w += ww[u] * v[u].w;
            }
        }
        // remainder
        for (; k < cnt; k++) {
            int   rr = __shfl_sync(0xffffffffu, r, k);
            float ww = __shfl_sync(0xffffffffu, w, k);
            float4 v = *(const float4*)(g_H + rr * 128 + lane * 4);
            acc.x += ww * v.x;
            acc.y += ww * v.y;
            acc.z += ww * v.z;
            acc.w += ww * v.w;
        }
    }
    acc.x *= di; acc.y *= di; acc.z *= di; acc.w *= di;

    const int c4 = lane * 4;
    if (layer == 1) {
        float4 b = *(const float4*)(bA + c4);
        float4 h;
        h.x = fmaxf(acc.x + b.x, 0.f);
        h.y = fmaxf(acc.y + b.y, 0.f);
        h.z = fmaxf(acc.z + b.z, 0.f);
        h.w = fmaxf(acc.w + b.w, 0.f);
        *(float4*)(g_hidden + i * 128 + c4) = h;
    } else {
        float4 b;
        float* dst;
        if (c4 < 64) {
            b = *(const float4*)(bA + c4);
            dst = out + i * 64 + c4;
        } else {
            b = *(const float4*)(bB + (c4 - 64));
            dst = out + NN * 64 + i * 64 + (c4 - 64);
        }
        float4 rr;
        rr.x = fmaxf(acc.x + b.x, 0.f);
        rr.y = fmaxf(acc.y + b.y, 0.f);
        rr.z = fmaxf(acc.z + b.z, 0.f);
        rr.w = fmaxf(acc.w + b.w, 0.f);
        *(float4*)dst = rr;
    }
}

// ---------------------------------------------------------------------------
extern "C" void kernel_launch(void* const* d_in, const int* in_sizes, int n_in,
                              void* d_out, int out_size) {
    const float* x  = (const float*)d_in[0];
    const int*   ei = (const int*)d_in[1];   // int32 (JAX default, no x64)
    const float* W1 = (const float*)d_in[2];
    const float* b1 = (const float*)d_in[3];
    const float* W2 = (const float*)d_in[4];
    const float* b2 = (const float*)d_in[5];
    const float* W3 = (const float*)d_in[6];
    const float* b3 = (const float*)d_in[7];
    float* out = (float*)d_out;

    const int gemm_blocks = (NN + 63) / 64;      // 782
    const int agg_blocks  = (NN + 7) / 8;        // 8 warps/block, 1 node/warp

    // CSR build (shared by both layers) + dinv ; pack W23
    zero_cnt_kernel<<<(NN + 255) / 256, 256>>>();
    hist_kernel<<<(NE + 255) / 256, 256>>>(ei);
    scan_kernel<<<1, 1024>>>();
    fill_kernel<<<(NE + 255) / 256, 256>>>(ei);
    packW_kernel<<<(128 * 32 + 255) / 256, 256>>>(W2, W3);

    // Layer 1: H = x@W1 ; agg -> hidden (bias+relu fused)
    gemm_kernel<<<gemm_blocks, 256>>>(x, W1, 0, 0);
    agg_kernel<<<agg_blocks, 256>>>(1, b1, nullptr, nullptr);

    // Layers 2+3 fused: H = hidden@[W2|W3] ; agg -> out (bias+relu+split fused)
    gemm_kernel<<<gemm_blocks, 256>>>(nullptr, nullptr, 1, 1);
    agg_kernel<<<agg_blocks, 256>>>(2, b2, b3, out);
}

// round 7
// speedup vs baseline: 1.0455x; 1.0455x over previous
#include <cuda_runtime.h>
#include <cuda_bf16.h>
#include <cstdint>

#define NN 50000
#define NE 800000

__device__ int   g_cnt[NN];
__device__ int   g_off[NN + 1];
__device__ int   g_cur[NN];
__device__ int   g_csr_row[NE];
__device__ float g_dinv[NN];
__device__ float g_H[NN * 128];      // linear output of current layer
__device__ float g_hidden[NN * 128]; // relu(layer1) activations
__device__ float g_W23[128 * 128];   // packed [W2 | W3]

// ---------------------------------------------------------------------------
// CSR build: histogram -> scan (+dinv) -> fill
// ---------------------------------------------------------------------------
__global__ void zero_cnt_kernel() {
    int i = blockIdx.x * blockDim.x + threadIdx.x;
    if (i < NN) g_cnt[i] = 0;
}

__global__ void hist_kernel(const int* __restrict__ ei) {
    int e = blockIdx.x * blockDim.x + threadIdx.x;
    if (e < NE) atomicAdd(&g_cnt[ei[NE + e]], 1);
}

__global__ void scan_kernel() {
    __shared__ int ssum[1024];
    const int t = threadIdx.x;
    const int CH = (NN + 1023) / 1024;  // 49
    int lo = t * CH;
    int hi = min(lo + CH, NN);
    int sum = 0;
    for (int k = lo; k < hi; k++) sum += g_cnt[k];
    ssum[t] = sum;
    __syncthreads();
    for (int d = 1; d < 1024; d <<= 1) {
        int v = ssum[t];
        int add = (t >= d) ? ssum[t - d] : 0;
        __syncthreads();
        ssum[t] = v + add;
        __syncthreads();
    }
    int run = (t > 0) ? ssum[t - 1] : 0;
    for (int k = lo; k < hi; k++) {
        g_off[k] = run;
        g_cur[k] = run;
        g_dinv[k] = rsqrtf((float)(1 + g_cnt[k]));
        run += g_cnt[k];
    }
    if (t == 1023) g_off[NN] = run;
}

__global__ void fill_kernel(const int* __restrict__ ei) {
    int e = blockIdx.x * blockDim.x + threadIdx.x;
    if (e < NE) {
        int row = ei[e];
        int col = ei[NE + e];
        int pos = atomicAdd(&g_cur[col], 1);
        g_csr_row[pos] = row;
    }
}

__global__ void packW_kernel(const float* __restrict__ W2,
                             const float* __restrict__ W3) {
    int i = blockIdx.x * blockDim.x + threadIdx.x;  // 128*32 float4
    if (i < 128 * 32) {
        int k  = i >> 5;
        int c4 = (i & 31) << 2;
        float4 v;
        if (c4 < 64) v = *(const float4*)(W2 + k * 64 + c4);
        else         v = *(const float4*)(W3 + k * 64 + (c4 - 64));
        ((float4*)g_W23)[i] = v;
    }
}

// ---------------------------------------------------------------------------
// tf32 tensor-core GEMM: g_H = X @ W.
// X [NN,128] (x or g_hidden), W [128,128] (W1 or g_W23), both staged in smem
// pre-converted to tf32 (cvt.rna) with stride 132 to avoid bank conflicts.
// Block: 128 threads (4 warps), 64 rows x 128 cols; warp = 16 rows x 128 cols.
// mma.sync.m16n8k8 tf32, fp32 accumulate.
// A-fragment (PTX ISA): a0=(g,tig) a1=(g+8,tig) a2=(g,tig+4) a3=(g+8,tig+4)
// B-fragment: b0=(k=tig, n=g) b1=(k=tig+4, n=g)
// C: c0,c1=(g, 2tig..+1)  c2,c3=(g+8, 2tig..+1)
// ---------------------------------------------------------------------------
#define XS 132          // padded row stride (floats)
#define GEMM_SMEM ((64 * XS + 128 * XS) * 4)

__device__ __forceinline__ uint32_t f2tf32(float f) {
    uint32_t r;
    asm("cvt.rna.tf32.f32 %0, %1;" : "=r"(r) : "f"(f));
    return r;
}

__global__ __launch_bounds__(128, 2)
void gemm_tc_kernel(const float* __restrict__ Xin,
                    const float* __restrict__ Win,
                    int use_hidden, int use_w23) {
    extern __shared__ uint32_t sm[];
    uint32_t* sX = sm;              // [64][132]
    uint32_t* sW = sm + 64 * XS;    // [128][132]

    const float* X = use_hidden ? g_hidden : Xin;
    const float* W = use_w23 ? g_W23 : Win;

    const int tid  = threadIdx.x;
    const int warp = tid >> 5;
    const int lane = tid & 31;
    const int g    = lane >> 2;     // group 0..7
    const int tig  = lane & 3;      // thread-in-group 0..3
    const int row0 = blockIdx.x * 64;

    // Stage W (128x128) -> tf32 smem
    for (int i = tid; i < 128 * 128; i += 128) {
        int k = i >> 7, n = i & 127;
        sW[k * XS + n] = f2tf32(W[i]);
    }
    // Stage X tile (64x128) -> tf32 smem (zero-pad OOB rows)
    for (int i = tid; i < 64 * 128; i += 128) {
        int r = i >> 7, c = i & 127;
        int row = row0 + r;
        float v = (row < NN) ? X[row * 128 + c] : 0.f;
        sX[r * XS + c] = f2tf32(v);
    }
    __syncthreads();

    float acc[16][4];
#pragma unroll
    for (int nt = 0; nt < 16; nt++)
#pragma unroll
        for (int c = 0; c < 4; c++) acc[nt][c] = 0.f;

    const int rA0 = warp * 16 + g;       // A rows g and g+8 within warp tile
#pragma unroll
    for (int k0 = 0; k0 < 128; k0 += 8) {
        uint32_t a0 = sX[rA0 * XS + k0 + tig];            // (g,   k+tig)
        uint32_t a1 = sX[(rA0 + 8) * XS + k0 + tig];      // (g+8, k+tig)
        uint32_t a2 = sX[rA0 * XS + k0 + tig + 4];        // (g,   k+tig+4)
        uint32_t a3 = sX[(rA0 + 8) * XS + k0 + tig + 4];  // (g+8, k+tig+4)
#pragma unroll
        for (int nt = 0; nt < 16; nt++) {
            uint32_t b0 = sW[(k0 + tig) * XS + nt * 8 + g];
            uint32_t b1 = sW[(k0 + tig + 4) * XS + nt * 8 + g];
            asm volatile(
                "mma.sync.aligned.m16n8k8.row.col.f32.tf32.tf32.f32 "
                "{%0,%1,%2,%3}, {%4,%5,%6,%7}, {%8,%9}, {%0,%1,%2,%3};"
                : "+f"(acc[nt][0]), "+f"(acc[nt][1]),
                  "+f"(acc[nt][2]), "+f"(acc[nt][3])
                : "r"(a0), "r"(a1), "r"(a2), "r"(a3), "r"(b0), "r"(b1));
        }
    }

    int rowA = row0 + rA0;
    int rowB = rowA + 8;
#pragma unroll
    for (int nt = 0; nt < 16; nt++) {
        int col = nt * 8 + tig * 2;
        if (rowA < NN)
            *(float2*)(g_H + rowA * 128 + col) = make_float2(acc[nt][0], acc[nt][1]);
        if (rowB < NN)
            *(float2*)(g_H + rowB * 128 + col) = make_float2(acc[nt][2], acc[nt][3]);
    }
}

// ---------------------------------------------------------------------------
// CSR aggregation, fused epilogue. One warp per target node, 4-wide gather MLP.
//   res = dinv[i] * ( dinv[i]*H[i] + sum_e dinv[row_e]*H[row_e] )
// ---------------------------------------------------------------------------
__global__ void agg_kernel(int layer,
                           const float* __restrict__ bA,
                           const float* __restrict__ bB,
                           float* __restrict__ out) {
    int warp = (blockIdx.x * blockDim.x + threadIdx.x) >> 5;
    if (warp >= NN) return;
    const int lane = threadIdx.x & 31;
    const int i = warp;
    const int s = g_off[i];
    const int e = g_off[i + 1];
    const float di = g_dinv[i];

    float4 hv = *(const float4*)(g_H + i * 128 + lane * 4);
    float4 acc = make_float4(hv.x * di, hv.y * di, hv.z * di, hv.w * di);

    for (int base = s; base < e; base += 32) {
        int j = base + lane;
        int r = 0;
        float w = 0.f;
        if (j < e) { r = g_csr_row[j]; w = g_dinv[r]; }
        int cnt = min(32, e - base);
        int k = 0;
        for (; k + 4 <= cnt; k += 4) {
            int rr[4]; float ww[4];
#pragma unroll
            for (int u = 0; u < 4; u++) {
                rr[u] = __shfl_sync(0xffffffffu, r, k + u);
                ww[u] = __shfl_sync(0xffffffffu, w, k + u);
            }
            float4 v[4];
#pragma unroll
            for (int u = 0; u < 4; u++)
                v[u] = *(const float4*)(g_H + rr[u] * 128 + lane * 4);
#pragma unroll
            for (int u = 0; u < 4; u++) {
                acc.x += ww[u] * v[u].x;
                acc.y += ww[u] * v[u].y;
                acc.z += ww[u] * v[u].z;
                acc.w += ww[u] * v[u].w;
            }
        }
        for (; k < cnt; k++) {
            int   rr = __shfl_sync(0xffffffffu, r, k);
            float ww = __shfl_sync(0xffffffffu, w, k);
            float4 v = *(const float4*)(g_H + rr * 128 + lane * 4);
            acc.x += ww * v.x;
            acc.y += ww * v.y;
            acc.z += ww * v.z;
            acc.w += ww * v.w;
        }
    }
    acc.x *= di; acc.y *= di; acc.z *= di; acc.w *= di;

    const int c4 = lane * 4;
    if (layer == 1) {
        float4 b = *(const float4*)(bA + c4);
        float4 h;
        h.x = fmaxf(acc.x + b.x, 0.f);
        h.y = fmaxf(acc.y + b.y, 0.f);
        h.z = fmaxf(acc.z + b.z, 0.f);
        h.w = fmaxf(acc.w + b.w, 0.f);
        *(float4*)(g_hidden + i * 128 + c4) = h;
    } else {
        float4 b;
        float* dst;
        if (c4 < 64) {
            b = *(const float4*)(bA + c4);
            dst = out + i * 64 + c4;
        } else {
            b = *(const float4*)(bB + (c4 - 64));
            dst = out + NN * 64 + i * 64 + (c4 - 64);
        }
        float4 rr;
        rr.x = fmaxf(acc.x + b.x, 0.f);
        rr.y = fmaxf(acc.y + b.y, 0.f);
        rr.z = fmaxf(acc.z + b.z, 0.f);
        rr.w = fmaxf(acc.w + b.w, 0.f);
        *(float4*)dst = rr;
    }
}

// ---------------------------------------------------------------------------
extern "C" void kernel_launch(void* const* d_in, const int* in_sizes, int n_in,
                              void* d_out, int out_size) {
    const float* x  = (const float*)d_in[0];
    const int*   ei = (const int*)d_in[1];   // int32 (JAX default, no x64)
    const float* W1 = (const float*)d_in[2];
    const float* b1 = (const float*)d_in[3];
    const float* W2 = (const float*)d_in[4];
    const float* b2 = (const float*)d_in[5];
    const float* W3 = (const float*)d_in[6];
    const float* b3 = (const float*)d_in[7];
    float* out = (float*)d_out;

    cudaFuncSetAttribute(gemm_tc_kernel,
                         cudaFuncAttributeMaxDynamicSharedMemorySize, GEMM_SMEM);

    const int gemm_blocks = (NN + 63) / 64;      // 782
    const int agg_blocks  = (NN + 7) / 8;        // 8 warps/block

    // CSR build + dinv ; pack W23
    zero_cnt_kernel<<<(NN + 255) / 256, 256>>>();
    hist_kernel<<<(NE + 255) / 256, 256>>>(ei);
    scan_kernel<<<1, 1024>>>();
    fill_kernel<<<(NE + 255) / 256, 256>>>(ei);
    packW_kernel<<<(128 * 32 + 255) / 256, 256>>>(W2, W3);

    // Layer 1
    gemm_tc_kernel<<<gemm_blocks, 128, GEMM_SMEM>>>(x, W1, 0, 0);
    agg_kernel<<<agg_blocks, 256>>>(1, b1, nullptr, nullptr);

    // Layers 2+3 fused
    gemm_tc_kernel<<<gemm_blocks, 128, GEMM_SMEM>>>(nullptr, nullptr, 1, 1);
    agg_kernel<<<agg_blocks, 256>>>(2, b2, b3, out);
}

// round 9
// speedup vs baseline: 1.2366x; 1.1827x over previous
#include <cuda_runtime.h>
#include <cuda_bf16.h>
#include <cstdint>

#define NN 50000
#define NE 800000

__device__ int      g_cnt[NN];
__device__ int      g_off[NN + 1];
__device__ int      g_cur[NN];
__device__ int      g_csr_row[NE];
__device__ float    g_dinv[NN];
__device__ float    g_H[NN * 128];        // fp32 linear output of current layer
__device__ uint32_t g_hidden[NN * 128];   // relu(layer1), stored as tf32 bits
__device__ uint32_t g_Xtf[NN * 128];      // x pre-converted to tf32
__device__ uint32_t g_Wtf1[128 * 128];    // W1 as tf32
__device__ uint32_t g_Wtf23[128 * 128];   // [W2|W3] as tf32

__device__ __forceinline__ uint32_t f2tf32(float f) {
    uint32_t r;
    asm("cvt.rna.tf32.f32 %0, %1;" : "=r"(r) : "f"(f));
    return r;
}

// ---------------------------------------------------------------------------
// CSR build: histogram -> scan (+dinv) -> fill
// ---------------------------------------------------------------------------
__global__ void zero_cnt_kernel() {
    int i = blockIdx.x * blockDim.x + threadIdx.x;
    if (i < NN) g_cnt[i] = 0;
}

__global__ void hist_kernel(const int* __restrict__ ei) {
    int e = blockIdx.x * blockDim.x + threadIdx.x;
    if (e < NE) atomicAdd(&g_cnt[ei[NE + e]], 1);
}

__global__ void scan_kernel() {
    __shared__ int ssum[1024];
    const int t = threadIdx.x;
    const int CH = (NN + 1023) / 1024;  // 49
    int lo = t * CH;
    int hi = min(lo + CH, NN);
    int sum = 0;
    for (int k = lo; k < hi; k++) sum += g_cnt[k];
    ssum[t] = sum;
    __syncthreads();
    for (int d = 1; d < 1024; d <<= 1) {
        int v = ssum[t];
        int add = (t >= d) ? ssum[t - d] : 0;
        __syncthreads();
        ssum[t] = v + add;
        __syncthreads();
    }
    int run = (t > 0) ? ssum[t - 1] : 0;
    for (int k = lo; k < hi; k++) {
        g_off[k] = run;
        g_cur[k] = run;
        g_dinv[k] = rsqrtf((float)(1 + g_cnt[k]));
        run += g_cnt[k];
    }
    if (t == 1023) g_off[NN] = run;
}

__global__ void fill_kernel(const int* __restrict__ ei) {
    int e = blockIdx.x * blockDim.x + threadIdx.x;
    if (e < NE) {
        int row = ei[e];
        int col = ei[NE + e];
        int pos = atomicAdd(&g_cur[col], 1);
        g_csr_row[pos] = row;
    }
}

// ---------------------------------------------------------------------------
// One-time tf32 conversions: x -> g_Xtf ; W1 -> g_Wtf1 ; [W2|W3] -> g_Wtf23
// ---------------------------------------------------------------------------
__global__ void cvtX_kernel(const float* __restrict__ x) {
    int i = blockIdx.x * blockDim.x + threadIdx.x;  // over NN*32 float4
    if (i < NN * 32) {
        float4 v = ((const float4*)x)[i];
        uint4 u;
        u.x = f2tf32(v.x); u.y = f2tf32(v.y);
        u.z = f2tf32(v.z); u.w = f2tf32(v.w);
        ((uint4*)g_Xtf)[i] = u;
    }
}

__global__ void packW_kernel(const float* __restrict__ W1,
                             const float* __restrict__ W2,
                             const float* __restrict__ W3) {
    int i = blockIdx.x * blockDim.x + threadIdx.x;
    if (i < 128 * 32) {
        float4 v = ((const float4*)W1)[i];
        uint4 u;
        u.x = f2tf32(v.x); u.y = f2tf32(v.y);
        u.z = f2tf32(v.z); u.w = f2tf32(v.w);
        ((uint4*)g_Wtf1)[i] = u;
    } else if (i < 2 * 128 * 32) {
        int j = i - 128 * 32;
        int k  = j >> 5;
        int c4 = (j & 31) << 2;
        float4 v;
        if (c4 < 64) v = *(const float4*)(W2 + k * 64 + c4);
        else         v = *(const float4*)(W3 + k * 64 + (c4 - 64));
        uint4 u;
        u.x = f2tf32(v.x); u.y = f2tf32(v.y);
        u.z = f2tf32(v.z); u.w = f2tf32(v.w);
        ((uint4*)g_Wtf23)[j] = u;
    }
}

// ---------------------------------------------------------------------------
// tf32 tensor-core GEMM: g_H = X @ W, operands pre-converted to tf32.
// layer_sel==0: X=g_Xtf, W=g_Wtf1 ; layer_sel==1: X=g_hidden, W=g_Wtf23.
// (Globals referenced in DEVICE code — host-side symbol names are invalid.)
// Staging = pure uint4 copies. Pad 136: bank = 8*tig + g -> conflict-free.
// Block: 128 threads (4 warps), 64 rows x 128 cols; warp = 16 rows x 128 cols.
// A-frag: a0=(g,tig) a1=(g+8,tig) a2=(g,tig+4) a3=(g+8,tig+4)
// B-frag: b0=(k=tig,n=g) b1=(k=tig+4,n=g); C: rows g/g+8, cols 2tig..+1.
// ---------------------------------------------------------------------------
#define XS 136
#define GEMM_SMEM ((64 * XS + 128 * XS) * 4)

__global__ __launch_bounds__(128, 2)
void gemm_tc_kernel(int layer_sel) {
    extern __shared__ uint32_t sm[];
    uint32_t* sX = sm;              // [64][136]
    uint32_t* sW = sm + 64 * XS;    // [128][136]

    const uint32_t* X = layer_sel ? g_hidden : g_Xtf;
    const uint32_t* W = layer_sel ? g_Wtf23 : g_Wtf1;

    const int tid  = threadIdx.x;
    const int warp = tid >> 5;
    const int lane = tid & 31;
    const int g    = lane >> 2;
    const int tig  = lane & 3;
    const int row0 = blockIdx.x * 64;

    // Stage W (128x128): 4096 uint4 / 128 threads = 32 iters
    for (int i = tid; i < 4096; i += 128) {
        int k = i >> 5;
        int n4 = (i & 31) << 2;
        uint4 u = ((const uint4*)W)[i];
        *(uint4*)(sW + k * XS + n4) = u;
    }
    // Stage X tile (64x128): 2048 uint4 / 128 threads = 16 iters
    for (int i = tid; i < 2048; i += 128) {
        int r = i >> 5;
        int c4 = (i & 31) << 2;
        int row = row0 + r;
        uint4 u = make_uint4(0u, 0u, 0u, 0u);
        if (row < NN) u = ((const uint4*)X)[row * 32 + (i & 31)];
        *(uint4*)(sX + r * XS + c4) = u;
    }
    __syncthreads();

    float acc[16][4];
#pragma unroll
    for (int nt = 0; nt < 16; nt++)
#pragma unroll
        for (int c = 0; c < 4; c++) acc[nt][c] = 0.f;

    const int rA0 = warp * 16 + g;
#pragma unroll
    for (int k0 = 0; k0 < 128; k0 += 8) {
        uint32_t a0 = sX[rA0 * XS + k0 + tig];
        uint32_t a1 = sX[(rA0 + 8) * XS + k0 + tig];
        uint32_t a2 = sX[rA0 * XS + k0 + tig + 4];
        uint32_t a3 = sX[(rA0 + 8) * XS + k0 + tig + 4];
#pragma unroll
        for (int nt = 0; nt < 16; nt++) {
            uint32_t b0 = sW[(k0 + tig) * XS + nt * 8 + g];
            uint32_t b1 = sW[(k0 + tig + 4) * XS + nt * 8 + g];
            asm volatile(
                "mma.sync.aligned.m16n8k8.row.col.f32.tf32.tf32.f32 "
                "{%0,%1,%2,%3}, {%4,%5,%6,%7}, {%8,%9}, {%0,%1,%2,%3};"
                : "+f"(acc[nt][0]), "+f"(acc[nt][1]),
                  "+f"(acc[nt][2]), "+f"(acc[nt][3])
                : "r"(a0), "r"(a1), "r"(a2), "r"(a3), "r"(b0), "r"(b1));
        }
    }

    int rowA = row0 + rA0;
    int rowB = rowA + 8;
#pragma unroll
    for (int nt = 0; nt < 16; nt++) {
        int col = nt * 8 + tig * 2;
        if (rowA < NN)
            *(float2*)(g_H + rowA * 128 + col) = make_float2(acc[nt][0], acc[nt][1]);
        if (rowB < NN)
            *(float2*)(g_H + rowB * 128 + col) = make_float2(acc[nt][2], acc[nt][3]);
    }
}

// ---------------------------------------------------------------------------
// CSR aggregation, fused epilogue. One warp per target node, 4-wide gather MLP.
//   res = dinv[i] * ( dinv[i]*H[i] + sum_e dinv[row_e]*H[row_e] )
// layer 1: g_hidden[i] = tf32(relu(res + b1))   (consumed only by gemm2)
// layer 2: out split with b2/b3 + relu
// ---------------------------------------------------------------------------
__global__ void agg_kernel(int layer,
                           const float* __restrict__ bA,
                           const float* __restrict__ bB,
                           float* __restrict__ out) {
    int warp = (blockIdx.x * blockDim.x + threadIdx.x) >> 5;
    if (warp >= NN) return;
    const int lane = threadIdx.x & 31;
    const int i = warp;
    const int s = g_off[i];
    const int e = g_off[i + 1];
    const float di = g_dinv[i];

    float4 hv = *(const float4*)(g_H + i * 128 + lane * 4);
    float4 acc = make_float4(hv.x * di, hv.y * di, hv.z * di, hv.w * di);

    for (int base = s; base < e; base += 32) {
        int j = base + lane;
        int r = 0;
        float w = 0.f;
        if (j < e) { r = g_csr_row[j]; w = g_dinv[r]; }
        int cnt = min(32, e - base);
        int k = 0;
        for (; k + 4 <= cnt; k += 4) {
            int rr[4]; float ww[4];
#pragma unroll
            for (int u = 0; u < 4; u++) {
                rr[u] = __shfl_sync(0xffffffffu, r, k + u);
                ww[u] = __shfl_sync(0xffffffffu, w, k + u);
            }
            float4 v[4];
#pragma unroll
            for (int u = 0; u < 4; u++)
                v[u] = *(const float4*)(g_H + rr[u] * 128 + lane * 4);
#pragma unroll
            for (int u = 0; u < 4; u++) {
                acc.x += ww[u] * v[u].x;
                acc.y += ww[u] * v[u].y;
                acc.z += ww[u] * v[u].z;
                acc.w += ww[u] * v[u].w;
            }
        }
        for (; k < cnt; k++) {
            int   rr = __shfl_sync(0xffffffffu, r, k);
            float ww = __shfl_sync(0xffffffffu, w, k);
            float4 v = *(const float4*)(g_H + rr * 128 + lane * 4);
            acc.x += ww * v.x;
            acc.y += ww * v.y;
            acc.z += ww * v.z;
            acc.w += ww * v.w;
        }
    }
    acc.x *= di; acc.y *= di; acc.z *= di; acc.w *= di;

    const int c4 = lane * 4;
    if (layer == 1) {
        float4 b = *(const float4*)(bA + c4);
        uint4 h;
        h.x = f2tf32(fmaxf(acc.x + b.x, 0.f));
        h.y = f2tf32(fmaxf(acc.y + b.y, 0.f));
        h.z = f2tf32(fmaxf(acc.z + b.z, 0.f));
        h.w = f2tf32(fmaxf(acc.w + b.w, 0.f));
        *(uint4*)(g_hidden + i * 128 + c4) = h;
    } else {
        float4 b;
        float* dst;
        if (c4 < 64) {
            b = *(const float4*)(bA + c4);
            dst = out + i * 64 + c4;
        } else {
            b = *(const float4*)(bB + (c4 - 64));
            dst = out + NN * 64 + i * 64 + (c4 - 64);
        }
        float4 rr;
        rr.x = fmaxf(acc.x + b.x, 0.f);
        rr.y = fmaxf(acc.y + b.y, 0.f);
        rr.z = fmaxf(acc.z + b.z, 0.f);
        rr.w = fmaxf(acc.w + b.w, 0.f);
        *(float4*)dst = rr;
    }
}

// ---------------------------------------------------------------------------
extern "C" void kernel_launch(void* const* d_in, const int* in_sizes, int n_in,
                              void* d_out, int out_size) {
    const float* x  = (const float*)d_in[0];
    const int*   ei = (const int*)d_in[1];   // int32 (JAX default, no x64)
    const float* W1 = (const float*)d_in[2];
    const float* b1 = (const float*)d_in[3];
    const float* W2 = (const float*)d_in[4];
    const float* b2 = (const float*)d_in[5];
    const float* W3 = (const float*)d_in[6];
    const float* b3 = (const float*)d_in[7];
    float* out = (float*)d_out;

    cudaFuncSetAttribute(gemm_tc_kernel,
                         cudaFuncAttributeMaxDynamicSharedMemorySize, GEMM_SMEM);

    const int gemm_blocks = (NN + 63) / 64;      // 782
    const int agg_blocks  = (NN + 7) / 8;        // 8 warps/block

    // Launch order puts gemm_tc at kernel index 3 (the one ncu captures).
    zero_cnt_kernel<<<(NN + 255) / 256, 256>>>();                      // 0
    cvtX_kernel<<<(NN * 32 + 255) / 256, 256>>>(x);                    // 1
    packW_kernel<<<(2 * 128 * 32 + 255) / 256, 256>>>(W1, W2, W3);     // 2
    gemm_tc_kernel<<<gemm_blocks, 128, GEMM_SMEM>>>(0);                // 3 <- profiled
    hist_kernel<<<(NE + 255) / 256, 256>>>(ei);                        // 4
    scan_kernel<<<1, 1024>>>();                                        // 5
    fill_kernel<<<(NE + 255) / 256, 256>>>(ei);                        // 6
    agg_kernel<<<agg_blocks, 256>>>(1, b1, nullptr, nullptr);          // 7
    gemm_tc_kernel<<<gemm_blocks, 128, GEMM_SMEM>>>(1);                // 8
    agg_kernel<<<agg_blocks, 256>>>(2, b2, b3, out);                   // 9
}

// round 10
// speedup vs baseline: 1.2927x; 1.0454x over previous
#include <cuda_runtime.h>
#include <cuda_bf16.h>
#include <cstdint>

#define NN 50000
#define NE 800000

__device__ int      g_cnt[NN];
__device__ int      g_off[NN + 1];
__device__ int      g_cur[NN];
__device__ int      g_csr_row[NE];
__device__ float    g_dinv[NN];
__device__ float    g_H[NN * 128];        // fp32 linear output of current layer
__device__ uint32_t g_hidden[NN * 128];   // relu(layer1), stored as tf32 bits
__device__ uint32_t g_Xtf[NN * 128];      // x pre-converted to tf32
__device__ uint32_t g_Wtf1[128 * 128];    // W1 as tf32
__device__ uint32_t g_Wtf23[128 * 128];   // [W2|W3] as tf32

__device__ __forceinline__ uint32_t f2tf32(float f) {
    uint32_t r;
    asm("cvt.rna.tf32.f32 %0, %1;" : "=r"(r) : "f"(f));
    return r;
}

// ---------------------------------------------------------------------------
// CSR build: histogram -> scan (+dinv) -> fill
// ---------------------------------------------------------------------------
__global__ void zero_cnt_kernel() {
    int i = blockIdx.x * blockDim.x + threadIdx.x;
    if (i < NN) g_cnt[i] = 0;
}

__global__ void hist_kernel(const int* __restrict__ ei) {
    int e = blockIdx.x * blockDim.x + threadIdx.x;
    if (e < NE) atomicAdd(&g_cnt[ei[NE + e]], 1);
}

__global__ void scan_kernel() {
    __shared__ int ssum[1024];
    const int t = threadIdx.x;
    const int CH = (NN + 1023) / 1024;  // 49
    int lo = t * CH;
    int hi = min(lo + CH, NN);
    int sum = 0;
    for (int k = lo; k < hi; k++) sum += g_cnt[k];
    ssum[t] = sum;
    __syncthreads();
    for (int d = 1; d < 1024; d <<= 1) {
        int v = ssum[t];
        int add = (t >= d) ? ssum[t - d] : 0;
        __syncthreads();
        ssum[t] = v + add;
        __syncthreads();
    }
    int run = (t > 0) ? ssum[t - 1] : 0;
    for (int k = lo; k < hi; k++) {
        g_off[k] = run;
        g_cur[k] = run;
        g_dinv[k] = rsqrtf((float)(1 + g_cnt[k]));
        run += g_cnt[k];
    }
    if (t == 1023) g_off[NN] = run;
}

__global__ void fill_kernel(const int* __restrict__ ei) {
    int e = blockIdx.x * blockDim.x + threadIdx.x;
    if (e < NE) {
        int row = ei[e];
        int col = ei[NE + e];
        int pos = atomicAdd(&g_cur[col], 1);
        g_csr_row[pos] = row;
    }
}

// ---------------------------------------------------------------------------
// One-time tf32 conversions
// ---------------------------------------------------------------------------
__global__ void cvtX_kernel(const float* __restrict__ x) {
    int i = blockIdx.x * blockDim.x + threadIdx.x;
    if (i < NN * 32) {
        float4 v = ((const float4*)x)[i];
        uint4 u;
        u.x = f2tf32(v.x); u.y = f2tf32(v.y);
        u.z = f2tf32(v.z); u.w = f2tf32(v.w);
        ((uint4*)g_Xtf)[i] = u;
    }
}

__global__ void packW_kernel(const float* __restrict__ W1,
                             const float* __restrict__ W2,
                             const float* __restrict__ W3) {
    int i = blockIdx.x * blockDim.x + threadIdx.x;
    if (i < 128 * 32) {
        float4 v = ((const float4*)W1)[i];
        uint4 u;
        u.x = f2tf32(v.x); u.y = f2tf32(v.y);
        u.z = f2tf32(v.z); u.w = f2tf32(v.w);
        ((uint4*)g_Wtf1)[i] = u;
    } else if (i < 2 * 128 * 32) {
        int j = i - 128 * 32;
        int k  = j >> 5;
        int c4 = (j & 31) << 2;
        float4 v;
        if (c4 < 64) v = *(const float4*)(W2 + k * 64 + c4);
        else         v = *(const float4*)(W3 + k * 64 + (c4 - 64));
        uint4 u;
        u.x = f2tf32(v.x); u.y = f2tf32(v.y);
        u.z = f2tf32(v.z); u.w = f2tf32(v.w);
        ((uint4*)g_Wtf23)[j] = u;
    }
}

// ---------------------------------------------------------------------------
// tf32 tensor-core GEMM: g_H = X @ W, operands pre-converted to tf32.
// 384 threads (12 warps), 192 rows x 128 cols per block; warp = 16 rows.
// W in smem PERMUTED: sW[k*132 + (n&7)*16 + (n>>3)] = W[k][n], so a thread's
// 16 B-fragment values (n = nt*8+g, nt=0..15) for fixed k are contiguous ->
// 8x LDS.128 per k-step instead of 32x LDS.32.
// Pad 132 => row offset = 4*tig (mod 32): A loads bank 4g+tig (conflict-free),
// B vector loads conflict-free per phase.
// A-frag: a0=(g,tig) a1=(g+8,tig) a2=(g,tig+4) a3=(g+8,tig+4)
// B-frag: b0=(k=tig,n) b1=(k=tig+4,n); C: rows g/g+8, cols 2tig..+1.
// ---------------------------------------------------------------------------
#define XS 132
#define MROWS 192
#define GEMM_SMEM ((MROWS * XS + 128 * XS) * 4)

__global__ __launch_bounds__(384, 1)
void gemm_tc_kernel(int layer_sel) {
    extern __shared__ uint32_t sm[];
    uint32_t* sX = sm;                 // [192][132]
    uint32_t* sW = sm + MROWS * XS;    // [128][132] permuted

    const uint32_t* X = layer_sel ? g_hidden : g_Xtf;
    const uint32_t* W = layer_sel ? g_Wtf23 : g_Wtf1;

    const int tid  = threadIdx.x;
    const int warp = tid >> 5;
    const int lane = tid & 31;
    const int g    = lane >> 2;
    const int tig  = lane & 3;
    const int row0 = blockIdx.x * MROWS;

    // Stage W (128x128) permuted: 4096 uint4 reads, scatter 4 scalars each
    for (int i = tid; i < 4096; i += 384) {
        int k  = i >> 5;
        int n0 = (i & 31) << 2;
        uint4 u = ((const uint4*)W)[i];
        uint32_t* wr = sW + k * XS;
        wr[((n0 + 0) & 7) * 16 + ((n0 + 0) >> 3)] = u.x;
        wr[((n0 + 1) & 7) * 16 + ((n0 + 1) >> 3)] = u.y;
        wr[((n0 + 2) & 7) * 16 + ((n0 + 2) >> 3)] = u.z;
        wr[((n0 + 3) & 7) * 16 + ((n0 + 3) >> 3)] = u.w;
    }
    // Stage X tile (192x128): 6144 uint4 / 384 threads = 16 iters
    for (int i = tid; i < MROWS * 32; i += 384) {
        int r  = i >> 5;
        int c4 = (i & 31) << 2;
        int row = row0 + r;
        uint4 u = make_uint4(0u, 0u, 0u, 0u);
        if (row < NN) u = ((const uint4*)X)[row * 32 + (i & 31)];
        *(uint4*)(sX + r * XS + c4) = u;
    }
    __syncthreads();

    float acc[16][4];
#pragma unroll
    for (int nt = 0; nt < 16; nt++)
#pragma unroll
        for (int c = 0; c < 4; c++) acc[nt][c] = 0.f;

    const int rA0 = warp * 16 + g;
#pragma unroll
    for (int k0 = 0; k0 < 128; k0 += 8) {
        uint32_t a0 = sX[rA0 * XS + k0 + tig];
        uint32_t a1 = sX[(rA0 + 8) * XS + k0 + tig];
        uint32_t a2 = sX[rA0 * XS + k0 + tig + 4];
        uint32_t a3 = sX[(rA0 + 8) * XS + k0 + tig + 4];
        const uint32_t* w0 = sW + (k0 + tig) * XS + g * 16;
        const uint32_t* w1 = sW + (k0 + tig + 4) * XS + g * 16;
#pragma unroll
        for (int c = 0; c < 4; c++) {
            uint4 b0v = *(const uint4*)(w0 + c * 4);
            uint4 b1v = *(const uint4*)(w1 + c * 4);
#pragma unroll
            for (int j = 0; j < 4; j++) {
                uint32_t b0 = (j == 0) ? b0v.x : (j == 1) ? b0v.y
                             : (j == 2) ? b0v.z : b0v.w;
                uint32_t b1 = (j == 0) ? b1v.x : (j == 1) ? b1v.y
                             : (j == 2) ? b1v.z : b1v.w;
                int nt = c * 4 + j;
                asm volatile(
                    "mma.sync.aligned.m16n8k8.row.col.f32.tf32.tf32.f32 "
                    "{%0,%1,%2,%3}, {%4,%5,%6,%7}, {%8,%9}, {%0,%1,%2,%3};"
                    : "+f"(acc[nt][0]), "+f"(acc[nt][1]),
                      "+f"(acc[nt][2]), "+f"(acc[nt][3])
                    : "r"(a0), "r"(a1), "r"(a2), "r"(a3), "r"(b0), "r"(b1));
            }
        }
    }

    int rowA = row0 + rA0;
    int rowB = rowA + 8;
#pragma unroll
    for (int nt = 0; nt < 16; nt++) {
        int col = nt * 8 + tig * 2;
        if (rowA < NN)
            *(float2*)(g_H + rowA * 128 + col) = make_float2(acc[nt][0], acc[nt][1]);
        if (rowB < NN)
            *(float2*)(g_H + rowB * 128 + col) = make_float2(acc[nt][2], acc[nt][3]);
    }
}

// ---------------------------------------------------------------------------
// CSR aggregation, fused epilogue. One warp per target node, 4-wide gather MLP.
//   res = dinv[i] * ( dinv[i]*H[i] + sum_e dinv[row_e]*H[row_e] )
// layer 1: g_hidden[i] = tf32(relu(res + b1))   (consumed only by gemm2)
// layer 2: out split with b2/b3 + relu
// ---------------------------------------------------------------------------
__global__ void agg_kernel(int layer,
                           const float* __restrict__ bA,
                           const float* __restrict__ bB,
                           float* __restrict__ out) {
    int warp = (blockIdx.x * blockDim.x + threadIdx.x) >> 5;
    if (warp >= NN) return;
    const int lane = threadIdx.x & 31;
    const int i = warp;
    const int s = g_off[i];
    const int e = g_off[i + 1];
    const float di = g_dinv[i];

    float4 hv = *(const float4*)(g_H + i * 128 + lane * 4);
    float4 acc = make_float4(hv.x * di, hv.y * di, hv.z * di, hv.w * di);

    for (int base = s; base < e; base += 32) {
        int j = base + lane;
        int r = 0;
        float w = 0.f;
        if (j < e) { r = g_csr_row[j]; w = g_dinv[r]; }
        int cnt = min(32, e - base);
        int k = 0;
        for (; k + 4 <= cnt; k += 4) {
            int rr[4]; float ww[4];
#pragma unroll
            for (int u = 0; u < 4; u++) {
                rr[u] = __shfl_sync(0xffffffffu, r, k + u);
                ww[u] = __shfl_sync(0xffffffffu, w, k + u);
            }
            float4 v[4];
#pragma unroll
            for (int u = 0; u < 4; u++)
                v[u] = *(const float4*)(g_H + rr[u] * 128 + lane * 4);
#pragma unroll
            for (int u = 0; u < 4; u++) {
                acc.x += ww[u] * v[u].x;
                acc.y += ww[u] * v[u].y;
                acc.z += ww[u] * v[u].z;
                acc.w += ww[u] * v[u].w;
            }
        }
        for (; k < cnt; k++) {
            int   rr = __shfl_sync(0xffffffffu, r, k);
            float ww = __shfl_sync(0xffffffffu, w, k);
            float4 v = *(const float4*)(g_H + rr * 128 + lane * 4);
            acc.x += ww * v.x;
            acc.y += ww * v.y;
            acc.z += ww * v.z;
            acc.w += ww * v.w;
        }
    }
    acc.x *= di; acc.y *= di; acc.z *= di; acc.w *= di;

    const int c4 = lane * 4;
    if (layer == 1) {
        float4 b = *(const float4*)(bA + c4);
        uint4 h;
        h.x = f2tf32(fmaxf(acc.x + b.x, 0.f));
        h.y = f2tf32(fmaxf(acc.y + b.y, 0.f));
        h.z = f2tf32(fmaxf(acc.z + b.z, 0.f));
        h.w = f2tf32(fmaxf(acc.w + b.w, 0.f));
        *(uint4*)(g_hidden + i * 128 + c4) = h;
    } else {
        float4 b;
        float* dst;
        if (c4 < 64) {
            b = *(const float4*)(bA + c4);
            dst = out + i * 64 + c4;
        } else {
            b = *(const float4*)(bB + (c4 - 64));
            dst = out + NN * 64 + i * 64 + (c4 - 64);
        }
        float4 rr;
        rr.x = fmaxf(acc.x + b.x, 0.f);
        rr.y = fmaxf(acc.y + b.y, 0.f);
        rr.z = fmaxf(acc.z + b.z, 0.f);
        rr.w = fmaxf(acc.w + b.w, 0.f);
        *(float4*)dst = rr;
    }
}

// ---------------------------------------------------------------------------
extern "C" void kernel_launch(void* const* d_in, const int* in_sizes, int n_in,
                              void* d_out, int out_size) {
    const float* x  = (const float*)d_in[0];
    const int*   ei = (const int*)d_in[1];   // int32 (JAX default, no x64)
    const float* W1 = (const float*)d_in[2];
    const float* b1 = (const float*)d_in[3];
    const float* W2 = (const float*)d_in[4];
    const float* b2 = (const float*)d_in[5];
    const float* W3 = (const float*)d_in[6];
    const float* b3 = (const float*)d_in[7];
    float* out = (float*)d_out;

    cudaFuncSetAttribute(gemm_tc_kernel,
                         cudaFuncAttributeMaxDynamicSharedMemorySize, GEMM_SMEM);

    const int gemm_blocks = (NN + MROWS - 1) / MROWS;  // 261
    const int agg_blocks  = (NN + 7) / 8;              // 8 warps/block

    // Launch order puts gemm_tc at kernel index 3 (the one ncu captures).
    zero_cnt_kernel<<<(NN + 255) / 256, 256>>>();                      // 0
    cvtX_kernel<<<(NN * 32 + 255) / 256, 256>>>(x);                    // 1
    packW_kernel<<<(2 * 128 * 32 + 255) / 256, 256>>>(W1, W2, W3);     // 2
    gemm_tc_kernel<<<gemm_blocks, 384, GEMM_SMEM>>>(0);                // 3 <- profiled
    hist_kernel<<<(NE + 255) / 256, 256>>>(ei);                        // 4
    scan_kernel<<<1, 1024>>>();                                        // 5
    fill_kernel<<<(NE + 255) / 256, 256>>>(ei);                        // 6
    agg_kernel<<<agg_blocks, 256>>>(1, b1, nullptr, nullptr);          // 7
    gemm_tc_kernel<<<gemm_blocks, 384, GEMM_SMEM>>>(1);                // 8
    agg_kernel<<<agg_blocks, 256>>>(2, b2, b3, out);                   // 9
}